// round 12
// baseline (speedup 1.0000x reference)
#include <cuda_runtime.h>
#include <cuda_fp16.h>
#include <cstdint>

// Problem constants (fixed by the dataset)
#define IN_F   4096
#define OUT_F  11008
#define NGROUP 32
#define M_MAX  8192

// Scratch (device globals: allocation-guard-safe)
__device__ __half g_WH[(size_t)OUT_F * IN_F];   // dequantized W, fp16, [OUT, IN] K-major
__device__ __half g_XH[(size_t)M_MAX * IN_F];   // x fp16, [M, IN]
__device__ int    g_is_f32;                     // 1 if scales/zeros delivered as fp32
__device__ unsigned g_tile_ctr;                 // work-stealing tile counter

// ---------------------------------------------------------------------------
// Kernel 0a: reset work counter (every launch — determinism)
// ---------------------------------------------------------------------------
__global__ void reset_kernel() { g_tile_ctr = 0; }

// ---------------------------------------------------------------------------
// Kernel 0b: detect dtype of scales/zeros (fp16 vs harness-promoted fp32)
// ---------------------------------------------------------------------------
__global__ void detect_kernel(const void* zeros) {
    const float* zf = (const float*)zeros;
    int f32 = 1;
    for (int i = 0; i < 64; i++) {
        float v = zf[i];
        if (!(v >= -0.5f && v <= 15.5f)) { f32 = 0; break; }  // NaN -> fp16
    }
    g_is_f32 = f32;
}

// ---------------------------------------------------------------------------
// Kernel 1: x fp32 -> fp16
// ---------------------------------------------------------------------------
__global__ void cvtx_kernel(const float* __restrict__ x, int n4) {
    int i = blockIdx.x * blockDim.x + threadIdx.x;
    if (i >= n4) return;
    float4 v = reinterpret_cast<const float4*>(x)[i];
    __half2 h0 = __floats2half2_rn(v.x, v.y);
    __half2 h1 = __floats2half2_rn(v.z, v.w);
    uint2 pk;
    pk.x = *reinterpret_cast<uint32_t*>(&h0);
    pk.y = *reinterpret_cast<uint32_t*>(&h1);
    *reinterpret_cast<uint2*>(g_XH + (size_t)i * 4) = pk;
}

// ---------------------------------------------------------------------------
// Kernel 2: dequantize W: w = (float(q) - z) * s -> fp16
// ---------------------------------------------------------------------------
__global__ void deq_kernel(const int* __restrict__ q,
                           const void* __restrict__ sc_raw,
                           const void* __restrict__ zr_raw) {
    int i = blockIdx.x * blockDim.x + threadIdx.x;
    if (i >= (OUT_F * IN_F) / 4) return;
    int o  = i >> 10;
    int k4 = i & 1023;
    int g  = k4 >> 5;
    int gidx = o * NGROUP + g;
    float s, z;
    if (g_is_f32) {
        s = ((const float*)sc_raw)[gidx];
        z = ((const float*)zr_raw)[gidx];
    } else {
        s = __half2float(((const __half*)sc_raw)[gidx]);
        z = __half2float(((const __half*)zr_raw)[gidx]);
    }
    size_t base = (size_t)i * 4;
    int4 qq = *reinterpret_cast<const int4*>(q + base);
    __half2 h0 = __floats2half2_rn(((float)qq.x - z) * s, ((float)qq.y - z) * s);
    __half2 h1 = __floats2half2_rn(((float)qq.z - z) * s, ((float)qq.w - z) * s);
    uint2 pk;
    pk.x = *reinterpret_cast<uint32_t*>(&h0);
    pk.y = *reinterpret_cast<uint32_t*>(&h1);
    *reinterpret_cast<uint2*>(g_WH + base) = pk;
}

// ---------------------------------------------------------------------------
// Kernel 3: persistent fp16 GEMM with work stealing.
// BM=128, BN=128, BK=64, 256 threads, 3-stage cp.async pipeline continuous
// ACROSS tiles, one __syncthreads per k-iter, ldmatrix + mma.sync.m16n8k16.
// Tile order: bn-panel swizzle (panel width 43) for L2 reuse of W.
// ---------------------------------------------------------------------------
#define BM 128
#define BN 128
#define BK 64
#define KTILES (IN_F / BK)                  // 64
#define NSTG 3
#define A_BYTES (BM * BK * 2)               // 16384
#define STG_BYTES (2 * A_BYTES)             // 32768 per stage (A + B)
#define SMEM_BYTES (NSTG * STG_BYTES + 16)  // stages + control word
#define CTRL_OFF (NSTG * STG_BYTES)
#define GRID_N (OUT_F / BN)                 // 86
#define GRID_M (M_MAX / BM)                 // 64
#define PANEL_W 43                          // 86 = 2 * 43
#define NTILES (GRID_N * GRID_M)            // 5504
#define NWORKERS 296                        // 2 CTAs x 148 SMs

__device__ __forceinline__ void cp_async16(uint32_t smem_addr, const void* gptr) {
    asm volatile("cp.async.cg.shared.global [%0], [%1], 16;\n"
                 :: "r"(smem_addr), "l"(gptr));
}

__device__ __forceinline__ void ldsm4(uint32_t& r0, uint32_t& r1, uint32_t& r2,
                                      uint32_t& r3, uint32_t addr) {
    asm volatile("ldmatrix.sync.aligned.m8n8.x4.shared.b16 {%0,%1,%2,%3}, [%4];\n"
                 : "=r"(r0), "=r"(r1), "=r"(r2), "=r"(r3) : "r"(addr));
}

__device__ __forceinline__ void mma16816(float* c, const uint32_t* a, const uint32_t* b) {
    asm volatile(
        "mma.sync.aligned.m16n8k16.row.col.f32.f16.f16.f32 "
        "{%0,%1,%2,%3}, {%4,%5,%6,%7}, {%8,%9}, {%0,%1,%2,%3};\n"
        : "+f"(c[0]), "+f"(c[1]), "+f"(c[2]), "+f"(c[3])
        : "r"(a[0]), "r"(a[1]), "r"(a[2]), "r"(a[3]), "r"(b[0]), "r"(b[1]));
}

// Decode tile id -> (bm, bn) under the bn-panel swizzle.
__device__ __forceinline__ void tile_decode(unsigned t, int& bm, int& bn) {
    unsigned p   = t / (PANEL_W * GRID_M);
    unsigned idx = t % (PANEL_W * GRID_M);
    bn = (int)(p * PANEL_W + idx % PANEL_W);
    bm = (int)(idx / PANEL_W);
}

// Issue one BKx(BM+BN) tile of cp.asyncs into stage `st` (one commit group)
__device__ __forceinline__ void load_stage(uint32_t smem_u, int st,
                                           const __half* gA, const __half* gB,
                                           int kt, int lr, int lc) {
    uint32_t bA = smem_u + (uint32_t)st * STG_BYTES;
    uint32_t bB = bA + A_BYTES;
    const int kbase = kt * BK + lc * 8;
#pragma unroll
    for (int p = 0; p < 4; p++) {
        int r = p * 32 + lr;
        int cs = lc ^ (r & 7);
        cp_async16(bA + (uint32_t)(r * 8 + cs) * 16, gA + (size_t)r * IN_F + kbase);
    }
#pragma unroll
    for (int p = 0; p < 4; p++) {
        int r = p * 32 + lr;
        int cs = lc ^ (r & 7);
        cp_async16(bB + (uint32_t)(r * 8 + cs) * 16, gB + (size_t)r * IN_F + kbase);
    }
    asm volatile("cp.async.commit_group;\n" ::: "memory");
}

__global__ __launch_bounds__(256, 2) void gemm_kernel(const float* __restrict__ bias,
                                                      float* __restrict__ out) {
    extern __shared__ __align__(128) char smem[];
    uint32_t smem_u = (uint32_t)__cvta_generic_to_shared(smem);
    unsigned* s_ctrl = (unsigned*)(smem + CTRL_OFF);

    const int tid  = threadIdx.x;
    const int lane = tid & 31;
    const int warp = tid >> 5;
    const int wm = warp & 1;        // 2 warps along M (64 rows each)
    const int wn = warp >> 1;       // 4 warps along N (32 cols each)

    // loader lane mapping
    const int lr = tid >> 3;
    const int lc = tid & 7;

    // fragment-read lane mapping
    const int a_r = wm * 64 + (lane & 15);
    const int a_c = lane >> 4;
    const int b_r = wn * 32 + (lane & 7) + ((lane >> 4) << 3);
    const int b_c = (lane >> 3) & 1;

    // grab first two tiles
    if (tid == 0) {
        s_ctrl[0] = atomicAdd(&g_tile_ctr, 1u);
        s_ctrl[1] = atomicAdd(&g_tile_ctr, 1u);
    }
    __syncthreads();
    unsigned cur = s_ctrl[0];
    unsigned nxt = s_ctrl[1];
    if (cur >= NTILES) return;   // uniform per CTA (can't happen at 296 workers)

    float acc[4][4][4];
#pragma unroll
    for (int i = 0; i < 4; i++)
#pragma unroll
        for (int j = 0; j < 4; j++)
#pragma unroll
            for (int k = 0; k < 4; k++) acc[i][j][k] = 0.0f;

    // prologue: stages 0,1 of first tile
    {
        int bm, bn;
        tile_decode(cur, bm, bn);
        const __half* gA = g_XH + (size_t)bm * BM * IN_F;
        const __half* gB = g_WH + (size_t)bn * BN * IN_F;
        load_stage(smem_u, 0, gA, gB, 0, lr, lc);
        load_stage(smem_u, 1, gA, gB, 1, lr, lc);
    }

    unsigned gkt = 0;
#pragma unroll 1
    while (true) {
        const int kt = (int)(gkt & 63u);
        asm volatile("cp.async.wait_group 1;\n" ::: "memory");
        __syncthreads();   // fences prior readers of the buffer we refill below

        // fetch a fresh "next tile" id once per tile (tid0), consumed at kt==32
        if (kt == 0 && gkt != 0 && tid == 0)
            s_ctrl[1] = atomicAdd(&g_tile_ctr, 1u);
        if (kt == 32)
            nxt = s_ctrl[1];

        // issue loads for iteration gkt+2 (possibly first stages of next tile)
        {
            int lkt = kt + 2;
            unsigned ltile = cur;
            if (lkt >= KTILES) { ltile = nxt; lkt -= KTILES; }
            if (ltile < NTILES) {
                int bm, bn;
                tile_decode(ltile, bm, bn);
                const __half* gA = g_XH + (size_t)bm * BM * IN_F;
                const __half* gB = g_WH + (size_t)bn * BN * IN_F;
                load_stage(smem_u, (int)((gkt + 2) % NSTG), gA, gB, lkt, lr, lc);
            } else {
                asm volatile("cp.async.commit_group;\n" ::: "memory");
            }
        }

        // compute on buffer gkt%3
        uint32_t bA = smem_u + (uint32_t)(gkt % NSTG) * STG_BYTES;
        uint32_t bB = bA + A_BYTES;
#pragma unroll
        for (int ks = 0; ks < 4; ks++) {
            uint32_t aF[4][4];
            uint32_t bF[4][2];
#pragma unroll
            for (int mt = 0; mt < 4; mt++) {
                int r = a_r + mt * 16;
                int ch = ks * 2 + a_c;
                ldsm4(aF[mt][0], aF[mt][1], aF[mt][2], aF[mt][3],
                      bA + (uint32_t)(r * 8 + (ch ^ (r & 7))) * 16);
            }
#pragma unroll
            for (int nt2 = 0; nt2 < 2; nt2++) {
                int r = b_r + nt2 * 16;
                int ch = ks * 2 + b_c;
                uint32_t t0, t1, t2, t3;
                ldsm4(t0, t1, t2, t3,
                      bB + (uint32_t)(r * 8 + (ch ^ (r & 7))) * 16);
                bF[2 * nt2][0] = t0; bF[2 * nt2][1] = t1;
                bF[2 * nt2 + 1][0] = t2; bF[2 * nt2 + 1][1] = t3;
            }
#pragma unroll
            for (int mt = 0; mt < 4; mt++)
#pragma unroll
                for (int nt = 0; nt < 4; nt++)
                    mma16816(acc[mt][nt], aF[mt], bF[nt]);
        }

        if (kt == KTILES - 1) {
            // epilogue for tile `cur` (overlaps with next tile's loads in flight)
            int bm, bn;
            tile_decode(cur, bm, bn);
            const int gm0 = bm * BM + wm * 64 + (lane >> 2);
            const int gn0 = bn * BN + wn * 32 + (lane & 3) * 2;
#pragma unroll
            for (int nt = 0; nt < 4; nt++) {
                int col = gn0 + nt * 8;
                float2 bb = *reinterpret_cast<const float2*>(bias + col);
#pragma unroll
                for (int mt = 0; mt < 4; mt++) {
                    int row = gm0 + mt * 16;
                    float2 v0 = { acc[mt][nt][0] + bb.x, acc[mt][nt][1] + bb.y };
                    float2 v1 = { acc[mt][nt][2] + bb.x, acc[mt][nt][3] + bb.y };
                    *reinterpret_cast<float2*>(out + (size_t)row * OUT_F + col) = v0;
                    *reinterpret_cast<float2*>(out + (size_t)(row + 8) * OUT_F + col) = v1;
                }
            }
#pragma unroll
            for (int i = 0; i < 4; i++)
#pragma unroll
                for (int j = 0; j < 4; j++)
#pragma unroll
                    for (int k = 0; k < 4; k++) acc[i][j][k] = 0.0f;

            cur = nxt;
            if (cur >= NTILES) break;   // uniform: all threads share cur/nxt
        }
        gkt++;
    }
    asm volatile("cp.async.wait_group 0;\n" ::: "memory");  // drain empties
}

// ---------------------------------------------------------------------------
// Launcher
// ---------------------------------------------------------------------------
extern "C" void kernel_launch(void* const* d_in, const int* in_sizes, int n_in,
                              void* d_out, int out_size) {
    const float* x    = (const float*)d_in[0];
    const int*   qw   = (const int*)d_in[1];
    const void*  sc   = d_in[2];
    const void*  zr   = d_in[3];
    const float* bias = (const float*)d_in[4];
    float* out = (float*)d_out;

    reset_kernel<<<1, 1>>>();
    detect_kernel<<<1, 1>>>(zr);

    const int n4x = in_sizes[0] / 4;
    cvtx_kernel<<<(n4x + 255) / 256, 256>>>(x, n4x);

    const int n4w = (OUT_F * IN_F) / 4;
    deq_kernel<<<(n4w + 255) / 256, 256>>>(qw, sc, zr);

    cudaFuncSetAttribute(gemm_kernel,
                         cudaFuncAttributeMaxDynamicSharedMemorySize, SMEM_BYTES);
    gemm_kernel<<<NWORKERS, 256, SMEM_BYTES>>>(bias, out);
}

// round 13
// speedup vs baseline: 1.0556x; 1.0556x over previous
#include <cuda_runtime.h>
#include <cuda_fp16.h>
#include <cstdint>

// Problem constants (fixed by the dataset)
#define IN_F   4096
#define OUT_F  11008
#define NGROUP 32
#define M_MAX  8192

// Scratch (device globals: allocation-guard-safe)
__device__ __half g_WH[(size_t)OUT_F * IN_F];   // dequantized W, fp16, [OUT, IN] K-major
__device__ __half g_XH[(size_t)M_MAX * IN_F];   // x fp16, [M, IN]
__device__ int    g_is_f32;                     // 1 if scales/zeros delivered as fp32

// ---------------------------------------------------------------------------
// Kernel 0: detect dtype of scales/zeros (fp16 vs harness-promoted fp32)
// ---------------------------------------------------------------------------
__global__ void detect_kernel(const void* zeros) {
    const float* zf = (const float*)zeros;
    int f32 = 1;
    for (int i = 0; i < 64; i++) {
        float v = zf[i];
        if (!(v >= -0.5f && v <= 15.5f)) { f32 = 0; break; }  // NaN -> fp16
    }
    g_is_f32 = f32;
}

// ---------------------------------------------------------------------------
// Kernel 1: x fp32 -> fp16
// ---------------------------------------------------------------------------
__global__ void cvtx_kernel(const float* __restrict__ x, int n4) {
    int i = blockIdx.x * blockDim.x + threadIdx.x;
    if (i >= n4) return;
    float4 v = reinterpret_cast<const float4*>(x)[i];
    __half2 h0 = __floats2half2_rn(v.x, v.y);
    __half2 h1 = __floats2half2_rn(v.z, v.w);
    uint2 pk;
    pk.x = *reinterpret_cast<uint32_t*>(&h0);
    pk.y = *reinterpret_cast<uint32_t*>(&h1);
    *reinterpret_cast<uint2*>(g_XH + (size_t)i * 4) = pk;
}

// ---------------------------------------------------------------------------
// Kernel 2: dequantize W: w = (float(q) - z) * s -> fp16
// ---------------------------------------------------------------------------
__global__ void deq_kernel(const int* __restrict__ q,
                           const void* __restrict__ sc_raw,
                           const void* __restrict__ zr_raw) {
    int i = blockIdx.x * blockDim.x + threadIdx.x;
    if (i >= (OUT_F * IN_F) / 4) return;
    int o  = i >> 10;
    int k4 = i & 1023;
    int g  = k4 >> 5;
    int gidx = o * NGROUP + g;
    float s, z;
    if (g_is_f32) {
        s = ((const float*)sc_raw)[gidx];
        z = ((const float*)zr_raw)[gidx];
    } else {
        s = __half2float(((const __half*)sc_raw)[gidx]);
        z = __half2float(((const __half*)zr_raw)[gidx]);
    }
    size_t base = (size_t)i * 4;
    int4 qq = *reinterpret_cast<const int4*>(q + base);
    __half2 h0 = __floats2half2_rn(((float)qq.x - z) * s, ((float)qq.y - z) * s);
    __half2 h1 = __floats2half2_rn(((float)qq.z - z) * s, ((float)qq.w - z) * s);
    uint2 pk;
    pk.x = *reinterpret_cast<uint32_t*>(&h0);
    pk.y = *reinterpret_cast<uint32_t*>(&h1);
    *reinterpret_cast<uint2*>(g_WH + base) = pk;
}

// ---------------------------------------------------------------------------
// Kernel 3: fp16 GEMM  out[m,n] = sum_k XH[m,k] * WH[n,k] + bias[n]
// BM=128, BN=128, BK=64, 256 threads, 3-stage cp.async pipeline,
// one __syncthreads per k-iter, ldmatrix + mma.sync.m16n8k16.
// 1D grid with bn-panel swizzle (panel width 43) for L2 reuse of W.
// Epilogue uses st.global.cs so output streams past L2 (protect W panel).
// ---------------------------------------------------------------------------
#define BM 128
#define BN 128
#define BK 64
#define KTILES (IN_F / BK)                  // 64
#define NSTG 3
#define A_BYTES (BM * BK * 2)               // 16384
#define STG_BYTES (2 * A_BYTES)             // 32768 per stage (A + B)
#define SMEM_BYTES (NSTG * STG_BYTES)       // 98304
#define GRID_N (OUT_F / BN)                 // 86
#define GRID_M (M_MAX / BM)                 // 64
#define PANEL_W 43                          // 86 = 2 * 43

__device__ __forceinline__ void cp_async16(uint32_t smem_addr, const void* gptr) {
    asm volatile("cp.async.cg.shared.global [%0], [%1], 16;\n"
                 :: "r"(smem_addr), "l"(gptr));
}

__device__ __forceinline__ void ldsm4(uint32_t& r0, uint32_t& r1, uint32_t& r2,
                                      uint32_t& r3, uint32_t addr) {
    asm volatile("ldmatrix.sync.aligned.m8n8.x4.shared.b16 {%0,%1,%2,%3}, [%4];\n"
                 : "=r"(r0), "=r"(r1), "=r"(r2), "=r"(r3) : "r"(addr));
}

__device__ __forceinline__ void mma16816(float* c, const uint32_t* a, const uint32_t* b) {
    asm volatile(
        "mma.sync.aligned.m16n8k16.row.col.f32.f16.f16.f32 "
        "{%0,%1,%2,%3}, {%4,%5,%6,%7}, {%8,%9}, {%0,%1,%2,%3};\n"
        : "+f"(c[0]), "+f"(c[1]), "+f"(c[2]), "+f"(c[3])
        : "r"(a[0]), "r"(a[1]), "r"(a[2]), "r"(a[3]), "r"(b[0]), "r"(b[1]));
}

__device__ __forceinline__ void stg_cs_v2(float* p, float a, float b) {
    asm volatile("st.global.cs.v2.f32 [%0], {%1, %2};\n"
                 :: "l"(p), "f"(a), "f"(b) : "memory");
}

// Issue one BKx(BM+BN) tile of cp.asyncs into stage `st` (one commit group)
__device__ __forceinline__ void load_stage(uint32_t smem_u, int st,
                                           const __half* gA, const __half* gB,
                                           int kt, int lr, int lc) {
    uint32_t bA = smem_u + (uint32_t)st * STG_BYTES;
    uint32_t bB = bA + A_BYTES;
    const int kbase = kt * BK + lc * 8;
#pragma unroll
    for (int p = 0; p < 4; p++) {
        int r = p * 32 + lr;
        int cs = lc ^ (r & 7);
        cp_async16(bA + (uint32_t)(r * 8 + cs) * 16, gA + (size_t)r * IN_F + kbase);
    }
#pragma unroll
    for (int p = 0; p < 4; p++) {
        int r = p * 32 + lr;
        int cs = lc ^ (r & 7);
        cp_async16(bB + (uint32_t)(r * 8 + cs) * 16, gB + (size_t)r * IN_F + kbase);
    }
    asm volatile("cp.async.commit_group;\n" ::: "memory");
}

__global__ __launch_bounds__(256, 2) void gemm_kernel(const float* __restrict__ bias,
                                                      float* __restrict__ out) {
    extern __shared__ __align__(128) __half smem[];
    uint32_t smem_u = (uint32_t)__cvta_generic_to_shared(smem);

    const int tid  = threadIdx.x;
    const int lane = tid & 31;
    const int warp = tid >> 5;
    const int wm = warp & 1;        // 2 warps along M (64 rows each)
    const int wn = warp >> 1;       // 4 warps along N (32 cols each)

    // bn-panel swizzle: panels of PANEL_W bn-columns; within a panel bn is
    // fastest so each wave touches <= PANEL_W MB of W, which stays in L2.
    const int bid = blockIdx.x;
    const int p   = bid / (PANEL_W * GRID_M);
    const int idx = bid % (PANEL_W * GRID_M);
    const size_t bn = (size_t)p * PANEL_W + (idx % PANEL_W);
    const size_t bm = idx / PANEL_W;

    const __half* gA = g_XH + bm * BM * IN_F;
    const __half* gB = g_WH + bn * BN * IN_F;

    // loader lane mapping: 32 rows x 8 chunks per 256-thread pass
    const int lr = tid >> 3;
    const int lc = tid & 7;

    // fragment-read lane mapping (ldmatrix address providers)
    const int a_r = wm * 64 + (lane & 15);
    const int a_c = lane >> 4;
    const int b_r = wn * 32 + (lane & 7) + ((lane >> 4) << 3);
    const int b_c = (lane >> 3) & 1;

    float acc[4][4][4];
#pragma unroll
    for (int i = 0; i < 4; i++)
#pragma unroll
        for (int j = 0; j < 4; j++)
#pragma unroll
            for (int k = 0; k < 4; k++) acc[i][j][k] = 0.0f;

    // prologue: stages 0, 1 in flight
    load_stage(smem_u, 0, gA, gB, 0, lr, lc);
    load_stage(smem_u, 1, gA, gB, 1, lr, lc);

#pragma unroll 1
    for (int kt = 0; kt < KTILES; kt++) {
        if (kt + 2 < KTILES)
            asm volatile("cp.async.wait_group 1;\n" ::: "memory");
        else
            asm volatile("cp.async.wait_group 0;\n" ::: "memory");
        __syncthreads();   // also fences compute(kt-1) readers of buf (kt+2)%3

        if (kt + 2 < KTILES)
            load_stage(smem_u, (kt + 2) % NSTG, gA, gB, kt + 2, lr, lc);

        uint32_t bA = smem_u + (uint32_t)(kt % NSTG) * STG_BYTES;
        uint32_t bB = bA + A_BYTES;

#pragma unroll
        for (int ks = 0; ks < 4; ks++) {
            uint32_t aF[4][4];
            uint32_t bF[4][2];
#pragma unroll
            for (int mt = 0; mt < 4; mt++) {
                int r = a_r + mt * 16;
                int ch = ks * 2 + a_c;
                ldsm4(aF[mt][0], aF[mt][1], aF[mt][2], aF[mt][3],
                      bA + (uint32_t)(r * 8 + (ch ^ (r & 7))) * 16);
            }
#pragma unroll
            for (int nt2 = 0; nt2 < 2; nt2++) {
                int r = b_r + nt2 * 16;
                int ch = ks * 2 + b_c;
                uint32_t t0, t1, t2, t3;
                ldsm4(t0, t1, t2, t3,
                      bB + (uint32_t)(r * 8 + (ch ^ (r & 7))) * 16);
                bF[2 * nt2][0] = t0; bF[2 * nt2][1] = t1;
                bF[2 * nt2 + 1][0] = t2; bF[2 * nt2 + 1][1] = t3;
            }
#pragma unroll
            for (int mt = 0; mt < 4; mt++)
#pragma unroll
                for (int nt = 0; nt < 4; nt++)
                    mma16816(acc[mt][nt], aF[mt], bF[nt]);
        }
    }

    // Epilogue: += bias, streaming fp32 stores (evict-first: out has no reuse,
    // keep the W panel resident in L2 for the other CTAs of this wave)
    const int gm0 = (int)bm * BM + wm * 64 + (lane >> 2);
    const int gn0 = (int)bn * BN + wn * 32 + (lane & 3) * 2;
#pragma unroll
    for (int nt = 0; nt < 4; nt++) {
        int col = gn0 + nt * 8;
        float2 bb;
        bb.x = __ldg(bias + col);
        bb.y = __ldg(bias + col + 1);
#pragma unroll
        for (int mt = 0; mt < 4; mt++) {
            int row = gm0 + mt * 16;
            stg_cs_v2(out + (size_t)row * OUT_F + col,
                      acc[mt][nt][0] + bb.x, acc[mt][nt][1] + bb.y);
            stg_cs_v2(out + (size_t)(row + 8) * OUT_F + col,
                      acc[mt][nt][2] + bb.x, acc[mt][nt][3] + bb.y);
        }
    }
}

// ---------------------------------------------------------------------------
// Launcher
// ---------------------------------------------------------------------------
extern "C" void kernel_launch(void* const* d_in, const int* in_sizes, int n_in,
                              void* d_out, int out_size) {
    const float* x    = (const float*)d_in[0];
    const int*   qw   = (const int*)d_in[1];
    const void*  sc   = d_in[2];
    const void*  zr   = d_in[3];
    const float* bias = (const float*)d_in[4];
    float* out = (float*)d_out;

    detect_kernel<<<1, 1>>>(zr);

    const int n4x = in_sizes[0] / 4;
    cvtx_kernel<<<(n4x + 255) / 256, 256>>>(x, n4x);

    const int n4w = (OUT_F * IN_F) / 4;
    deq_kernel<<<(n4w + 255) / 256, 256>>>(qw, sc, zr);

    cudaFuncSetAttribute(gemm_kernel,
                         cudaFuncAttributeMaxDynamicSharedMemorySize, SMEM_BYTES);
    gemm_kernel<<<GRID_N * GRID_M, 256, SMEM_BYTES>>>(bias, out);
}

// round 17
// speedup vs baseline: 1.0668x; 1.0106x over previous
#include <cuda_runtime.h>
#include <cuda_fp16.h>
#include <cstdint>

// Problem constants (fixed by the dataset)
#define IN_F   4096
#define OUT_F  11008
#define NGROUP 32
#define M_MAX  8192

// Scratch (device globals: allocation-guard-safe)
__device__ __half g_WH[(size_t)OUT_F * IN_F];   // dequantized W, fp16, [OUT, IN] K-major
__device__ __half g_XH[(size_t)M_MAX * IN_F];   // x fp16, [M, IN]
__device__ int    g_is_f32;                     // 1 if scales/zeros delivered as fp32

// ---------------------------------------------------------------------------
// Kernel 0: detect dtype of scales/zeros (fp16 vs harness-promoted fp32)
// ---------------------------------------------------------------------------
__global__ void detect_kernel(const void* zeros) {
    const float* zf = (const float*)zeros;
    int f32 = 1;
    for (int i = 0; i < 64; i++) {
        float v = zf[i];
        if (!(v >= -0.5f && v <= 15.5f)) { f32 = 0; break; }  // NaN -> fp16
    }
    g_is_f32 = f32;
}

// ---------------------------------------------------------------------------
// Kernel 1: x fp32 -> fp16, 8 elements per thread
// ---------------------------------------------------------------------------
__global__ void cvtx_kernel(const float* __restrict__ x, int n8) {
    int i = blockIdx.x * blockDim.x + threadIdx.x;
    if (i >= n8) return;
    const float4* xp = reinterpret_cast<const float4*>(x) + (size_t)i * 2;
    float4 v0 = xp[0];
    float4 v1 = xp[1];
    __half2 h0 = __floats2half2_rn(v0.x, v0.y);
    __half2 h1 = __floats2half2_rn(v0.z, v0.w);
    __half2 h2 = __floats2half2_rn(v1.x, v1.y);
    __half2 h3 = __floats2half2_rn(v1.z, v1.w);
    uint4 pk;
    pk.x = *reinterpret_cast<uint32_t*>(&h0);
    pk.y = *reinterpret_cast<uint32_t*>(&h1);
    pk.z = *reinterpret_cast<uint32_t*>(&h2);
    pk.w = *reinterpret_cast<uint32_t*>(&h3);
    *reinterpret_cast<uint4*>(g_XH + (size_t)i * 8) = pk;
}

// ---------------------------------------------------------------------------
// Kernel 2: dequantize W: w = (float(q) - z) * s -> fp16, 8 elements/thread
// 8 consecutive k stay within one group (group size 128, base k % 8 == 0).
// ---------------------------------------------------------------------------
__device__ __forceinline__ int4 ldg_cs_v4(const int* p) {
    int4 v;
    asm volatile("ld.global.cs.v4.s32 {%0,%1,%2,%3}, [%4];\n"
                 : "=r"(v.x), "=r"(v.y), "=r"(v.z), "=r"(v.w) : "l"(p));
    return v;
}

__global__ void deq_kernel(const int* __restrict__ q,
                           const void* __restrict__ sc_raw,
                           const void* __restrict__ zr_raw) {
    int i = blockIdx.x * blockDim.x + threadIdx.x;      // one thread per 8 elems
    if (i >= (OUT_F * IN_F) / 8) return;
    int o  = i >> 9;             // / (IN_F/8)
    int k8 = i & 511;
    int g  = k8 >> 4;            // (k8*8)/128
    int gidx = o * NGROUP + g;
    float s, z;
    if (g_is_f32) {
        s = ((const float*)sc_raw)[gidx];
        z = ((const float*)zr_raw)[gidx];
    } else {
        s = __half2float(((const __half*)sc_raw)[gidx]);
        z = __half2float(((const __half*)zr_raw)[gidx]);
    }
    size_t base = (size_t)i * 8;
    int4 q0 = ldg_cs_v4(q + base);
    int4 q1 = ldg_cs_v4(q + base + 4);
    __half2 h0 = __floats2half2_rn(((float)q0.x - z) * s, ((float)q0.y - z) * s);
    __half2 h1 = __floats2half2_rn(((float)q0.z - z) * s, ((float)q0.w - z) * s);
    __half2 h2 = __floats2half2_rn(((float)q1.x - z) * s, ((float)q1.y - z) * s);
    __half2 h3 = __floats2half2_rn(((float)q1.z - z) * s, ((float)q1.w - z) * s);
    uint4 pk;
    pk.x = *reinterpret_cast<uint32_t*>(&h0);
    pk.y = *reinterpret_cast<uint32_t*>(&h1);
    pk.z = *reinterpret_cast<uint32_t*>(&h2);
    pk.w = *reinterpret_cast<uint32_t*>(&h3);
    *reinterpret_cast<uint4*>(g_WH + base) = pk;
}

// ---------------------------------------------------------------------------
// Kernel 3: fp16 GEMM  out[m,n] = sum_k XH[m,k] * WH[n,k] + bias[n]
// BM=128, BN=128, BK=64, 256 threads, 3-stage cp.async pipeline,
// one __syncthreads per k-iter, ldmatrix + mma.sync.m16n8k16.
// 1D grid with bn-panel swizzle (panel width 43) for L2 reuse of W.
// ---------------------------------------------------------------------------
#define BM 128
#define BN 128
#define BK 64
#define KTILES (IN_F / BK)                  // 64
#define NSTG 3
#define A_BYTES (BM * BK * 2)               // 16384
#define STG_BYTES (2 * A_BYTES)             // 32768 per stage (A + B)
#define SMEM_BYTES (NSTG * STG_BYTES)       // 98304
#define GRID_N (OUT_F / BN)                 // 86
#define GRID_M (M_MAX / BM)                 // 64
#define PANEL_W 43                          // 86 = 2 * 43

__device__ __forceinline__ void cp_async16(uint32_t smem_addr, const void* gptr) {
    asm volatile("cp.async.cg.shared.global [%0], [%1], 16;\n"
                 :: "r"(smem_addr), "l"(gptr));
}

__device__ __forceinline__ void ldsm4(uint32_t& r0, uint32_t& r1, uint32_t& r2,
                                      uint32_t& r3, uint32_t addr) {
    asm volatile("ldmatrix.sync.aligned.m8n8.x4.shared.b16 {%0,%1,%2,%3}, [%4];\n"
                 : "=r"(r0), "=r"(r1), "=r"(r2), "=r"(r3) : "r"(addr));
}

__device__ __forceinline__ void mma16816(float* c, const uint32_t* a, const uint32_t* b) {
    asm volatile(
        "mma.sync.aligned.m16n8k16.row.col.f32.f16.f16.f32 "
        "{%0,%1,%2,%3}, {%4,%5,%6,%7}, {%8,%9}, {%0,%1,%2,%3};\n"
        : "+f"(c[0]), "+f"(c[1]), "+f"(c[2]), "+f"(c[3])
        : "r"(a[0]), "r"(a[1]), "r"(a[2]), "r"(a[3]), "r"(b[0]), "r"(b[1]));
}

// Issue one BKx(BM+BN) tile of cp.asyncs into stage `st` (one commit group)
__device__ __forceinline__ void load_stage(uint32_t smem_u, int st,
                                           const __half* gA, const __half* gB,
                                           int kt, int lr, int lc) {
    uint32_t bA = smem_u + (uint32_t)st * STG_BYTES;
    uint32_t bB = bA + A_BYTES;
    const int kbase = kt * BK + lc * 8;
#pragma unroll
    for (int p = 0; p < 4; p++) {
        int r = p * 32 + lr;
        int cs = lc ^ (r & 7);
        cp_async16(bA + (uint32_t)(r * 8 + cs) * 16, gA + (size_t)r * IN_F + kbase);
    }
#pragma unroll
    for (int p = 0; p < 4; p++) {
        int r = p * 32 + lr;
        int cs = lc ^ (r & 7);
        cp_async16(bB + (uint32_t)(r * 8 + cs) * 16, gB + (size_t)r * IN_F + kbase);
    }
    asm volatile("cp.async.commit_group;\n" ::: "memory");
}

__global__ __launch_bounds__(256, 2) void gemm_kernel(const float* __restrict__ bias,
                                                      float* __restrict__ out) {
    extern __shared__ __align__(128) __half smem[];
    uint32_t smem_u = (uint32_t)__cvta_generic_to_shared(smem);

    const int tid  = threadIdx.x;
    const int lane = tid & 31;
    const int warp = tid >> 5;
    const int wm = warp & 1;        // 2 warps along M (64 rows each)
    const int wn = warp >> 1;       // 4 warps along N (32 cols each)

    // bn-panel swizzle: panels of PANEL_W bn-columns; within a panel bn is
    // fastest so each wave touches <= PANEL_W MB of W, which stays in L2.
    const int bid = blockIdx.x;
    const int p   = bid / (PANEL_W * GRID_M);
    const int idx = bid % (PANEL_W * GRID_M);
    const size_t bn = (size_t)p * PANEL_W + (idx % PANEL_W);
    const size_t bm = idx / PANEL_W;

    const __half* gA = g_XH + bm * BM * IN_F;
    const __half* gB = g_WH + bn * BN * IN_F;

    // loader lane mapping: 32 rows x 8 chunks per 256-thread pass
    const int lr = tid >> 3;
    const int lc = tid & 7;

    // fragment-read lane mapping (ldmatrix address providers)
    const int a_r = wm * 64 + (lane & 15);
    const int a_c = lane >> 4;
    const int b_r = wn * 32 + (lane & 7) + ((lane >> 4) << 3);
    const int b_c = (lane >> 3) & 1;

    float acc[4][4][4];
#pragma unroll
    for (int i = 0; i < 4; i++)
#pragma unroll
        for (int j = 0; j < 4; j++)
#pragma unroll
            for (int k = 0; k < 4; k++) acc[i][j][k] = 0.0f;

    // prologue: stages 0, 1 in flight
    load_stage(smem_u, 0, gA, gB, 0, lr, lc);
    load_stage(smem_u, 1, gA, gB, 1, lr, lc);

#pragma unroll 1
    for (int kt = 0; kt < KTILES; kt++) {
        if (kt + 2 < KTILES)
            asm volatile("cp.async.wait_group 1;\n" ::: "memory");
        else
            asm volatile("cp.async.wait_group 0;\n" ::: "memory");
        __syncthreads();   // also fences compute(kt-1) readers of buf (kt+2)%3

        if (kt + 2 < KTILES)
            load_stage(smem_u, (kt + 2) % NSTG, gA, gB, kt + 2, lr, lc);

        uint32_t bA = smem_u + (uint32_t)(kt % NSTG) * STG_BYTES;
        uint32_t bB = bA + A_BYTES;

#pragma unroll
        for (int ks = 0; ks < 4; ks++) {
            uint32_t aF[4][4];
            uint32_t bF[4][2];
#pragma unroll
            for (int mt = 0; mt < 4; mt++) {
                int r = a_r + mt * 16;
                int ch = ks * 2 + a_c;
                ldsm4(aF[mt][0], aF[mt][1], aF[mt][2], aF[mt][3],
                      bA + (uint32_t)(r * 8 + (ch ^ (r & 7))) * 16);
            }
#pragma unroll
            for (int nt2 = 0; nt2 < 2; nt2++) {
                int r = b_r + nt2 * 16;
                int ch = ks * 2 + b_c;
                uint32_t t0, t1, t2, t3;
                ldsm4(t0, t1, t2, t3,
                      bB + (uint32_t)(r * 8 + (ch ^ (r & 7))) * 16);
                bF[2 * nt2][0] = t0; bF[2 * nt2][1] = t1;
                bF[2 * nt2 + 1][0] = t2; bF[2 * nt2 + 1][1] = t3;
            }
#pragma unroll
            for (int mt = 0; mt < 4; mt++)
#pragma unroll
                for (int nt = 0; nt < 4; nt++)
                    mma16816(acc[mt][nt], aF[mt], bF[nt]);
        }
    }

    // Epilogue: += bias, fp32 stores (float2 per 8x8 quad-row)
    const int gm0 = (int)bm * BM + wm * 64 + (lane >> 2);
    const int gn0 = (int)bn * BN + wn * 32 + (lane & 3) * 2;
#pragma unroll
    for (int nt = 0; nt < 4; nt++) {
        int col = gn0 + nt * 8;
        float2 bb;
        bb.x = __ldg(bias + col);
        bb.y = __ldg(bias + col + 1);
#pragma unroll
        for (int mt = 0; mt < 4; mt++) {
            int row = gm0 + mt * 16;
            float2 v0 = { acc[mt][nt][0] + bb.x, acc[mt][nt][1] + bb.y };
            float2 v1 = { acc[mt][nt][2] + bb.x, acc[mt][nt][3] + bb.y };
            *reinterpret_cast<float2*>(out + (size_t)row * OUT_F + col) = v0;
            *reinterpret_cast<float2*>(out + (size_t)(row + 8) * OUT_F + col) = v1;
        }
    }
}

// ---------------------------------------------------------------------------
// Launcher
// ---------------------------------------------------------------------------
extern "C" void kernel_launch(void* const* d_in, const int* in_sizes, int n_in,
                              void* d_out, int out_size) {
    const float* x    = (const float*)d_in[0];
    const int*   qw   = (const int*)d_in[1];
    const void*  sc   = d_in[2];
    const void*  zr   = d_in[3];
    const float* bias = (const float*)d_in[4];
    float* out = (float*)d_out;

    detect_kernel<<<1, 1>>>(zr);

    const int n8x = in_sizes[0] / 8;
    cvtx_kernel<<<(n8x + 255) / 256, 256>>>(x, n8x);

    const int n8w = (OUT_F * IN_F) / 8;
    deq_kernel<<<(n8w + 255) / 256, 256>>>(qw, sc, zr);

    cudaFuncSetAttribute(gemm_kernel,
                         cudaFuncAttributeMaxDynamicSharedMemorySize, SMEM_BYTES);
    gemm_kernel<<<GRID_N * GRID_M, 256, SMEM_BYTES>>>(bias, out);
}